// round 8
// baseline (speedup 1.0000x reference)
#include <cuda_runtime.h>
#include <cuda_bf16.h>
#include <math.h>

#define B_   32
#define T_   512
#define H_   1024
#define G4   4096   // 4*H

#define NCTA      128
#define NTHREADS  256

// ---------------------------------------------------------------------------
// Persistent device scratch (no cudaMalloc allowed)
// ---------------------------------------------------------------------------
__device__ float g_xz[(size_t)B_ * T_ * G4];        // [B*T, 4H] input projection
__device__ __nv_bfloat16 g_hbf[2][B_ * H_];         // double-buffered hidden (bf16)
__device__ unsigned g_flags[NCTA * 8];              // per-CTA step stamps (32B stride)

// ---------------------------------------------------------------------------
// helpers
// ---------------------------------------------------------------------------
__device__ __forceinline__ void mma_bf16(float c[4],
                                         unsigned a0, unsigned a1, unsigned a2, unsigned a3,
                                         unsigned b0, unsigned b1) {
    asm volatile(
        "mma.sync.aligned.m16n8k16.row.col.f32.bf16.bf16.f32 "
        "{%0,%1,%2,%3}, {%4,%5,%6,%7}, {%8,%9}, {%0,%1,%2,%3};"
        : "+f"(c[0]), "+f"(c[1]), "+f"(c[2]), "+f"(c[3])
        : "r"(a0), "r"(a1), "r"(a2), "r"(a3), "r"(b0), "r"(b1));
}

__device__ __forceinline__ unsigned pack_bf16(float lo, float hi) {
    __nv_bfloat162 v = __floats2bfloat162_rn(lo, hi);
    return *(unsigned*)&v;
}

__device__ __forceinline__ float sigf(float v) {
    return __fdividef(1.0f, 1.0f + __expf(-v));
}
__device__ __forceinline__ float tanh_fast(float v) {
    return __fdividef(2.0f, 1.0f + __expf(-2.0f * v)) - 1.0f;
}

__device__ __forceinline__ void cp16(unsigned dst_smem, const void* src) {
    asm volatile("cp.async.cg.shared.global [%0], [%1], 16;"
                 :: "r"(dst_smem), "l"(src));
}

__device__ __forceinline__ unsigned ld_acq(const unsigned* p) {
    unsigned v;
    asm volatile("ld.acquire.gpu.global.b32 %0, [%1];" : "=r"(v) : "l"(p));
    return v;
}
__device__ __forceinline__ void st_rel(unsigned* p, unsigned v) {
    asm volatile("st.release.gpu.global.b32 [%0], %1;" :: "l"(p), "r"(v));
}

// ---------------------------------------------------------------------------
// Kernel 1: xz = x @ W + b  via bf16 m16n8k16 (CTA(0,0) also re-inits state).
// ---------------------------------------------------------------------------
#define AS32_STRIDE 12
#define BS32_STRIDE 68

__global__ __launch_bounds__(256) void xw_gemm(const float* __restrict__ X,
                                               const float* __restrict__ W,
                                               const float* __restrict__ bias) {
    __shared__ unsigned As32[64 * AS32_STRIDE];
    __shared__ unsigned Bs32[8 * BS32_STRIDE];

    const int tid   = threadIdx.x;
    const int lane  = tid & 31;
    const int w     = tid >> 5;
    const int g     = lane >> 2;
    const int tig   = lane & 3;
    const int warpM = w >> 2;
    const int warpN = w & 3;

    // ---- embedded per-replay state re-init (tiny, runs alongside GEMM) ----
    if (blockIdx.x == 0 && blockIdx.y == 0) {
        for (int i = tid; i < B_ * H_; i += 256)
            g_hbf[0][i] = __float2bfloat16(0.0f);
        for (int i = tid; i < NCTA * 8; i += 256)
            g_flags[i] = 0;
    }

    const int row0 = blockIdx.y * 64;
    const int col0 = blockIdx.x * 64;

    const int aRow = tid >> 2;
    const int aC   = tid & 3;
    const int bKp  = tid >> 4;
    const int bNq  = tid & 15;

    float acc[2][2][4];
#pragma unroll
    for (int i = 0; i < 2; i++)
#pragma unroll
        for (int j = 0; j < 2; j++)
#pragma unroll
            for (int k = 0; k < 4; k++) acc[i][j][k] = 0.0f;

    for (int k0 = 0; k0 < H_; k0 += 16) {
        {
            float4 av = *(const float4*)(X + (size_t)(row0 + aRow) * H_ + k0 + 4 * aC);
            uint2 p;
            p.x = pack_bf16(av.x, av.y);
            p.y = pack_bf16(av.z, av.w);
            *(uint2*)(As32 + aRow * AS32_STRIDE + 2 * aC) = p;
        }
        if (tid < 128) {
            const float* wr0 = W + (size_t)(k0 + 2 * bKp)     * G4 + col0 + 4 * bNq;
            const float* wr1 = W + (size_t)(k0 + 2 * bKp + 1) * G4 + col0 + 4 * bNq;
            float4 w0 = *(const float4*)wr0;
            float4 w1 = *(const float4*)wr1;
            uint4 p;
            p.x = pack_bf16(w0.x, w1.x);
            p.y = pack_bf16(w0.y, w1.y);
            p.z = pack_bf16(w0.z, w1.z);
            p.w = pack_bf16(w0.w, w1.w);
            *(uint4*)(Bs32 + bKp * BS32_STRIDE + 4 * bNq) = p;
        }
        __syncthreads();

        unsigned a[2][4];
#pragma unroll
        for (int mi = 0; mi < 2; mi++) {
            const int r = warpM * 32 + mi * 16 + g;
            a[mi][0] = As32[r * AS32_STRIDE + tig];
            a[mi][1] = As32[(r + 8) * AS32_STRIDE + tig];
            a[mi][2] = As32[r * AS32_STRIDE + tig + 4];
            a[mi][3] = As32[(r + 8) * AS32_STRIDE + tig + 4];
        }
#pragma unroll
        for (int ni = 0; ni < 2; ni++) {
            const int n = warpN * 16 + ni * 8 + g;
            unsigned b0 = Bs32[tig * BS32_STRIDE + n];
            unsigned b1 = Bs32[(tig + 4) * BS32_STRIDE + n];
#pragma unroll
            for (int mi = 0; mi < 2; mi++)
                mma_bf16(acc[mi][ni], a[mi][0], a[mi][1], a[mi][2], a[mi][3], b0, b1);
        }
        __syncthreads();
    }

#pragma unroll
    for (int mi = 0; mi < 2; mi++) {
#pragma unroll
        for (int ni = 0; ni < 2; ni++) {
            int row = row0 + warpM * 32 + mi * 16 + g;
            int col = col0 + warpN * 16 + ni * 8 + 2 * tig;
            float2 bvv = *(const float2*)(bias + col);
            float2 v0 = make_float2(acc[mi][ni][0] + bvv.x, acc[mi][ni][1] + bvv.y);
            float2 v1 = make_float2(acc[mi][ni][2] + bvv.x, acc[mi][ni][3] + bvv.y);
            *(float2*)(g_xz + (size_t)row * G4 + col)       = v0;
            *(float2*)(g_xz + (size_t)(row + 8) * G4 + col) = v1;
        }
    }
}

// ---------------------------------------------------------------------------
// Kernel 2: persistent LSTM recurrence.
// - U fragments in registers (per warp, whole kernel)
// - per-warp k-slice h staging via cp.async (no block sync before MMA)
// - one-hop flat flag barrier (every CTA polls all 128 flags)
// ---------------------------------------------------------------------------
#define HS_STRIDE  1032                    // bf16 units per row (1024 + 8 pad)
#define RED_STRIDE 40                      // floats -> conflict-free gate loads
#define HS_BYTES   (32 * HS_STRIDE * 2)
#define RED_BYTES  (8 * 32 * RED_STRIDE * 4)
#define SMEM_BYTES (HS_BYTES + RED_BYTES)

__global__ __launch_bounds__(NTHREADS, 1) void lstm_persistent(
        const float* __restrict__ U,
        const float* __restrict__ x,
        float* __restrict__ out) {
    extern __shared__ char smem[];
    __nv_bfloat16* hS = (__nv_bfloat16*)smem;
    float*        redS = (float*)(smem + HS_BYTES);
    const unsigned hS_base = (unsigned)__cvta_generic_to_shared(hS);

    const int tid  = threadIdx.x;
    const int lane = tid & 31;
    const int ks   = tid >> 5;    // warp id = k-slice (0..7), 128 k each
    const int g    = lane >> 2;
    const int tig  = lane & 3;

    const int d0 = blockIdx.x * 8;
    const int fidx = ((tid + blockIdx.x) & (NCTA - 1)) * 8;  // rotated flag slot

    // ---- preload this warp's U fragments into registers (one-time) ----
    unsigned breg[8][4][2];
#pragma unroll
    for (int kk = 0; kk < 8; kk++) {
#pragma unroll
        for (int ng = 0; ng < 4; ng++) {
            const int col = ng * H_ + d0 + g;
            const int k0  = ks * 128 + kk * 16 + 2 * tig;
            breg[kk][ng][0] = pack_bf16(U[(size_t)(k0    ) * G4 + col],
                                        U[(size_t)(k0 + 1) * G4 + col]);
            breg[kk][ng][1] = pack_bf16(U[(size_t)(k0 + 8) * G4 + col],
                                        U[(size_t)(k0 + 9) * G4 + col]);
        }
    }

    const int eb = tid >> 3;     // gate-phase batch
    const int ed = tid & 7;      // gate-phase local dim
    float c_reg = 0.0f;

    // prefetch xz + residual x for t = 0 (stream order covers xw_gemm writes)
    float zin[4];
#pragma unroll
    for (int gate = 0; gate < 4; gate++)
        zin[gate] = __ldcg(&g_xz[((size_t)eb * T_ + 0) * G4 + gate * H_ + d0 + ed]);
    size_t xi = ((size_t)eb * T_ + 0) * H_ + d0 + ed;
    float xres = __ldcg(&x[xi]);

    for (int t = 0; t < T_; t++) {
        const unsigned stamp = (unsigned)(t + 1);
        const __nv_bfloat16* hprev = g_hbf[t & 1];
        __nv_bfloat16*       hcur  = g_hbf[(t + 1) & 1];

        // ---- per-warp k-slice staging: warp ks loads h[:, ks*128 .. +128) ----
#pragma unroll
        for (int i = 0; i < 16; i++) {
            int q = i * 32 + lane;        // 0..511 chunk of warp's 8KB slice
            int r = q >> 4;               // batch row 0..31
            int c = q & 15;               // 16B chunk within 256B row-slice
            cp16(hS_base + (unsigned)(r * HS_STRIDE + ks * 128 + c * 8) * 2,
                 hprev + r * H_ + ks * 128 + c * 8);
        }
        asm volatile("cp.async.commit_group;");
        asm volatile("cp.async.wait_group 0;" ::: "memory");
        // no __syncthreads: each warp consumes only its own slice

        // ---- z partials: per warp [32 x 32] over its 128-k slice ----
        float acc[2][4][4];
#pragma unroll
        for (int mi = 0; mi < 2; mi++)
#pragma unroll
            for (int ng = 0; ng < 4; ng++)
#pragma unroll
                for (int q = 0; q < 4; q++) acc[mi][ng][q] = 0.0f;

#pragma unroll
        for (int kk = 0; kk < 8; kk++) {
            const int kcol = ks * 128 + kk * 16 + 2 * tig;
#pragma unroll
            for (int mi = 0; mi < 2; mi++) {
                const __nv_bfloat16* r0 = hS + (mi * 16 + g) * HS_STRIDE;
                const __nv_bfloat16* r1 = hS + (mi * 16 + g + 8) * HS_STRIDE;
                unsigned a0 = *(const unsigned*)(r0 + kcol);
                unsigned a1 = *(const unsigned*)(r1 + kcol);
                unsigned a2 = *(const unsigned*)(r0 + kcol + 8);
                unsigned a3 = *(const unsigned*)(r1 + kcol + 8);
#pragma unroll
                for (int ng = 0; ng < 4; ng++)
                    mma_bf16(acc[mi][ng], a0, a1, a2, a3,
                             breg[kk][ng][0], breg[kk][ng][1]);
            }
        }

        // ---- write k-partials ----
#pragma unroll
        for (int mi = 0; mi < 2; mi++) {
#pragma unroll
            for (int ng = 0; ng < 4; ng++) {
                const int col = ng * 8 + 2 * tig;
                float* r0 = redS + (ks * 32 + mi * 16 + g)     * RED_STRIDE + col;
                float* r1 = redS + (ks * 32 + mi * 16 + g + 8) * RED_STRIDE + col;
                *(float2*)r0 = make_float2(acc[mi][ng][0], acc[mi][ng][1]);
                *(float2*)r1 = make_float2(acc[mi][ng][2], acc[mi][ng][3]);
            }
        }
        __syncthreads();

        // ---- gates + state update ----
        const float* rb = redS + eb * RED_STRIDE + ed;
        float z[4];
#pragma unroll
        for (int gate = 0; gate < 4; gate++) {
            const float* p = rb + gate * 8;
            float s = zin[gate];
#pragma unroll
            for (int q = 0; q < 8; q++) s += p[q * 32 * RED_STRIDE];
            z[gate] = s;
        }
        float ig = sigf(z[0]);
        float fg = sigf(z[1]);
        float gg = tanh_fast(z[2]);
        float og = sigf(z[3]);

        c_reg = fg * c_reg + ig * gg;
        float hn = og * tanh_fast(c_reg);
        hcur[eb * H_ + d0 + ed] = __float2bfloat16(hn);

        // ---- publish h ----
        __syncthreads();                       // CTA's h chunk complete
        if (tid == 0) st_rel(&g_flags[blockIdx.x * 8], stamp);

        // ---- off-critical-path work while peers arrive ----
        out[xi] = tanh_fast(hn + xres);
        if (t + 1 < T_) {
#pragma unroll
            for (int gate = 0; gate < 4; gate++)
                zin[gate] = __ldcg(&g_xz[((size_t)eb * T_ + t + 1) * G4 + gate * H_ + d0 + ed]);
            xi = ((size_t)eb * T_ + t + 1) * H_ + d0 + ed;
            xres = __ldcg(&x[xi]);
        }

        // ---- one-hop flat barrier: all CTAs poll all flags ----
        if (tid < NCTA) {
            while (ld_acq(&g_flags[fidx]) < stamp) { }
        }
        __syncthreads();
    }
}

// ---------------------------------------------------------------------------
extern "C" void kernel_launch(void* const* d_in, const int* in_sizes, int n_in,
                              void* d_out, int out_size) {
    const float* x    = (const float*)d_in[0];
    const float* W    = (const float*)d_in[1];
    const float* U    = (const float*)d_in[2];
    const float* bias = (const float*)d_in[3];
    float* out        = (float*)d_out;

    cudaFuncSetAttribute(lstm_persistent,
                         cudaFuncAttributeMaxDynamicSharedMemorySize, SMEM_BYTES);

    dim3 grid_gemm(G4 / 64, (B_ * T_) / 64);   // (64, 256)
    xw_gemm<<<grid_gemm, 256>>>(x, W, bias);

    lstm_persistent<<<NCTA, NTHREADS, SMEM_BYTES>>>(U, x, out);
}

// round 9
// speedup vs baseline: 1.2223x; 1.2223x over previous
#include <cuda_runtime.h>
#include <cuda_bf16.h>
#include <math.h>

#define B_   32
#define T_   512
#define H_   1024
#define G4   4096   // 4*H

#define NCTA      128
#define NTHREADS  512
#define NW        16      // warps per CTA
#define KW        64      // k rows per warp

// ---------------------------------------------------------------------------
// Persistent device scratch (no cudaMalloc allowed)
// ---------------------------------------------------------------------------
__device__ float g_xz[(size_t)B_ * T_ * G4];        // [B*T, 4H] input projection
__device__ __nv_bfloat16 g_hbf[2][B_ * H_];         // double-buffered hidden (bf16)
__device__ unsigned g_flags[NCTA * 8];              // per-CTA step stamps (32B stride)

// ---------------------------------------------------------------------------
// helpers
// ---------------------------------------------------------------------------
__device__ __forceinline__ void mma_bf16(float c[4],
                                         unsigned a0, unsigned a1, unsigned a2, unsigned a3,
                                         unsigned b0, unsigned b1) {
    asm volatile(
        "mma.sync.aligned.m16n8k16.row.col.f32.bf16.bf16.f32 "
        "{%0,%1,%2,%3}, {%4,%5,%6,%7}, {%8,%9}, {%0,%1,%2,%3};"
        : "+f"(c[0]), "+f"(c[1]), "+f"(c[2]), "+f"(c[3])
        : "r"(a0), "r"(a1), "r"(a2), "r"(a3), "r"(b0), "r"(b1));
}

__device__ __forceinline__ unsigned pack_bf16(float lo, float hi) {
    __nv_bfloat162 v = __floats2bfloat162_rn(lo, hi);
    return *(unsigned*)&v;
}

__device__ __forceinline__ float sigf(float v) {
    return __fdividef(1.0f, 1.0f + __expf(-v));
}
__device__ __forceinline__ float tanh_fast(float v) {
    return __fdividef(2.0f, 1.0f + __expf(-2.0f * v)) - 1.0f;
}

__device__ __forceinline__ void cp16(unsigned dst_smem, const void* src) {
    asm volatile("cp.async.cg.shared.global [%0], [%1], 16;"
                 :: "r"(dst_smem), "l"(src));
}

__device__ __forceinline__ unsigned ld_acq(const unsigned* p) {
    unsigned v;
    asm volatile("ld.acquire.gpu.global.b32 %0, [%1];" : "=r"(v) : "l"(p));
    return v;
}
__device__ __forceinline__ void st_rel(unsigned* p, unsigned v) {
    asm volatile("st.release.gpu.global.b32 [%0], %1;" :: "l"(p), "r"(v));
}

// ---------------------------------------------------------------------------
// Kernel 1: xz = x @ W + b  via bf16 m16n8k16 (CTA(0,0) also re-inits state).
// ---------------------------------------------------------------------------
#define AS32_STRIDE 12
#define BS32_STRIDE 68

__global__ __launch_bounds__(256) void xw_gemm(const float* __restrict__ X,
                                               const float* __restrict__ W,
                                               const float* __restrict__ bias) {
    __shared__ unsigned As32[64 * AS32_STRIDE];
    __shared__ unsigned Bs32[8 * BS32_STRIDE];

    const int tid   = threadIdx.x;
    const int lane  = tid & 31;
    const int w     = tid >> 5;
    const int g     = lane >> 2;
    const int tig   = lane & 3;
    const int warpM = w >> 2;
    const int warpN = w & 3;

    // ---- embedded per-replay state re-init ----
    if (blockIdx.x == 0 && blockIdx.y == 0) {
        for (int i = tid; i < B_ * H_; i += 256)
            g_hbf[0][i] = __float2bfloat16(0.0f);
        for (int i = tid; i < NCTA * 8; i += 256)
            g_flags[i] = 0;
    }

    const int row0 = blockIdx.y * 64;
    const int col0 = blockIdx.x * 64;

    const int aRow = tid >> 2;
    const int aC   = tid & 3;
    const int bKp  = tid >> 4;
    const int bNq  = tid & 15;

    float acc[2][2][4];
#pragma unroll
    for (int i = 0; i < 2; i++)
#pragma unroll
        for (int j = 0; j < 2; j++)
#pragma unroll
            for (int k = 0; k < 4; k++) acc[i][j][k] = 0.0f;

    for (int k0 = 0; k0 < H_; k0 += 16) {
        {
            float4 av = *(const float4*)(X + (size_t)(row0 + aRow) * H_ + k0 + 4 * aC);
            uint2 p;
            p.x = pack_bf16(av.x, av.y);
            p.y = pack_bf16(av.z, av.w);
            *(uint2*)(As32 + aRow * AS32_STRIDE + 2 * aC) = p;
        }
        if (tid < 128) {
            const float* wr0 = W + (size_t)(k0 + 2 * bKp)     * G4 + col0 + 4 * bNq;
            const float* wr1 = W + (size_t)(k0 + 2 * bKp + 1) * G4 + col0 + 4 * bNq;
            float4 w0 = *(const float4*)wr0;
            float4 w1 = *(const float4*)wr1;
            uint4 p;
            p.x = pack_bf16(w0.x, w1.x);
            p.y = pack_bf16(w0.y, w1.y);
            p.z = pack_bf16(w0.z, w1.z);
            p.w = pack_bf16(w0.w, w1.w);
            *(uint4*)(Bs32 + bKp * BS32_STRIDE + 4 * bNq) = p;
        }
        __syncthreads();

        unsigned a[2][4];
#pragma unroll
        for (int mi = 0; mi < 2; mi++) {
            const int r = warpM * 32 + mi * 16 + g;
            a[mi][0] = As32[r * AS32_STRIDE + tig];
            a[mi][1] = As32[(r + 8) * AS32_STRIDE + tig];
            a[mi][2] = As32[r * AS32_STRIDE + tig + 4];
            a[mi][3] = As32[(r + 8) * AS32_STRIDE + tig + 4];
        }
#pragma unroll
        for (int ni = 0; ni < 2; ni++) {
            const int n = warpN * 16 + ni * 8 + g;
            unsigned b0 = Bs32[tig * BS32_STRIDE + n];
            unsigned b1 = Bs32[(tig + 4) * BS32_STRIDE + n];
#pragma unroll
            for (int mi = 0; mi < 2; mi++)
                mma_bf16(acc[mi][ni], a[mi][0], a[mi][1], a[mi][2], a[mi][3], b0, b1);
        }
        __syncthreads();
    }

#pragma unroll
    for (int mi = 0; mi < 2; mi++) {
#pragma unroll
        for (int ni = 0; ni < 2; ni++) {
            int row = row0 + warpM * 32 + mi * 16 + g;
            int col = col0 + warpN * 16 + ni * 8 + 2 * tig;
            float2 bvv = *(const float2*)(bias + col);
            float2 v0 = make_float2(acc[mi][ni][0] + bvv.x, acc[mi][ni][1] + bvv.y);
            float2 v1 = make_float2(acc[mi][ni][2] + bvv.x, acc[mi][ni][3] + bvv.y);
            *(float2*)(g_xz + (size_t)row * G4 + col)       = v0;
            *(float2*)(g_xz + (size_t)(row + 8) * G4 + col) = v1;
        }
    }
}

// ---------------------------------------------------------------------------
// Kernel 2: persistent LSTM recurrence, dataflow-synchronized.
// 128 CTAs x 512 threads (16 warps). CTA owns 8 hidden dims (32 z-cols).
// Warp w consumes only k rows [64w, 64w+64) of h, produced by CTAs
// 8w..8w+8  ->  warp waits ONLY on those 8 flags (4 lanes per flag,
// all lanes ld.acquire), then cp.asyncs its 4KB slice and MMAs.
// No global barrier anywhere. Publish = st.release of own flag.
// ---------------------------------------------------------------------------
#define HS_STRIDE  1032                    // bf16 units per row (1024 + 8 pad)
#define RED_STRIDE 40                      // floats -> conflict-free gate loads
#define HS_BYTES   (32 * HS_STRIDE * 2)
#define RED_BYTES  (NW * 32 * RED_STRIDE * 4)
#define SMEM_BYTES (HS_BYTES + RED_BYTES)

__global__ __launch_bounds__(NTHREADS, 1) void lstm_persistent(
        const float* __restrict__ U,
        const float* __restrict__ x,
        float* __restrict__ out) {
    extern __shared__ char smem[];
    __nv_bfloat16* hS = (__nv_bfloat16*)smem;
    float*        redS = (float*)(smem + HS_BYTES);
    const unsigned hS_base = (unsigned)__cvta_generic_to_shared(hS);

    const int tid  = threadIdx.x;
    const int lane = tid & 31;
    const int w    = tid >> 5;    // warp id = k-slice (0..15), 64 k each
    const int g    = lane >> 2;
    const int tig  = lane & 3;

    const int d0 = blockIdx.x * 8;
    // producer flag this lane polls: CTAs 8w .. 8w+7, 4 lanes per flag
    const unsigned* myflag = &g_flags[(8 * w + (lane & 7)) * 8];

    // ---- preload this warp's U fragments into registers (one-time) ----
    unsigned breg[4][4][2];
#pragma unroll
    for (int kk = 0; kk < 4; kk++) {
#pragma unroll
        for (int ng = 0; ng < 4; ng++) {
            const int col = ng * H_ + d0 + g;
            const int k0  = w * KW + kk * 16 + 2 * tig;
            breg[kk][ng][0] = pack_bf16(U[(size_t)(k0    ) * G4 + col],
                                        U[(size_t)(k0 + 1) * G4 + col]);
            breg[kk][ng][1] = pack_bf16(U[(size_t)(k0 + 8) * G4 + col],
                                        U[(size_t)(k0 + 9) * G4 + col]);
        }
    }

    const int eb = tid >> 3;     // gate-phase batch   (tid < 256 only)
    const int ed = tid & 7;      // gate-phase local dim
    float c_reg = 0.0f;

    // prefetch xz + residual x for t = 0 (stream order covers xw_gemm writes)
    float zin[4];
    size_t xi = 0;
    float xres = 0.0f;
    if (tid < 256) {
#pragma unroll
        for (int gate = 0; gate < 4; gate++)
            zin[gate] = __ldcg(&g_xz[((size_t)eb * T_ + 0) * G4 + gate * H_ + d0 + ed]);
        xi = ((size_t)eb * T_ + 0) * H_ + d0 + ed;
        xres = __ldcg(&x[xi]);
    }

    for (int t = 0; t < T_; t++) {
        const unsigned need = (unsigned)t;          // h_t available when flag >= t
        const __nv_bfloat16* hprev = g_hbf[t & 1];
        __nv_bfloat16*       hcur  = g_hbf[(t + 1) & 1];

        // ---- per-warp dataflow wait: only this warp's 8 producers ----
        for (;;) {
            unsigned v = ld_acq(myflag);
            if (__all_sync(0xffffffffu, v >= need)) break;
        }

        // ---- stage this warp's 4KB k-slice of h ----
#pragma unroll
        for (int i = 0; i < 8; i++) {
            int q = i * 32 + lane;        // 0..255 chunk id
            int r = q >> 3;               // batch row 0..31
            int c = q & 7;                // 16B chunk within 128B slice
            cp16(hS_base + (unsigned)(r * HS_STRIDE + w * KW + c * 8) * 2,
                 hprev + r * H_ + w * KW + c * 8);
        }
        asm volatile("cp.async.commit_group;");
        asm volatile("cp.async.wait_group 0;" ::: "memory");

        // ---- z partials: per warp [32 x 32] over its 64-k slice ----
        float acc[2][4][4];
#pragma unroll
        for (int mi = 0; mi < 2; mi++)
#pragma unroll
            for (int ng = 0; ng < 4; ng++)
#pragma unroll
                for (int q = 0; q < 4; q++) acc[mi][ng][q] = 0.0f;

#pragma unroll
        for (int kk = 0; kk < 4; kk++) {
            const int kcol = w * KW + kk * 16 + 2 * tig;
#pragma unroll
            for (int mi = 0; mi < 2; mi++) {
                const __nv_bfloat16* r0 = hS + (mi * 16 + g) * HS_STRIDE;
                const __nv_bfloat16* r1 = hS + (mi * 16 + g + 8) * HS_STRIDE;
                unsigned a0 = *(const unsigned*)(r0 + kcol);
                unsigned a1 = *(const unsigned*)(r1 + kcol);
                unsigned a2 = *(const unsigned*)(r0 + kcol + 8);
                unsigned a3 = *(const unsigned*)(r1 + kcol + 8);
#pragma unroll
                for (int ng = 0; ng < 4; ng++)
                    mma_bf16(acc[mi][ng], a0, a1, a2, a3,
                             breg[kk][ng][0], breg[kk][ng][1]);
            }
        }

        // ---- write k-partials ----
#pragma unroll
        for (int mi = 0; mi < 2; mi++) {
#pragma unroll
            for (int ng = 0; ng < 4; ng++) {
                const int col = ng * 8 + 2 * tig;
                float* r0 = redS + (w * 32 + mi * 16 + g)     * RED_STRIDE + col;
                float* r1 = redS + (w * 32 + mi * 16 + g + 8) * RED_STRIDE + col;
                *(float2*)r0 = make_float2(acc[mi][ng][0], acc[mi][ng][1]);
                *(float2*)r1 = make_float2(acc[mi][ng][2], acc[mi][ng][3]);
            }
        }
        __syncthreads();

        // ---- gates + state update (threads < 256) ----
        if (tid < 256) {
            const float* rb = redS + eb * RED_STRIDE + ed;
            float z[4];
#pragma unroll
            for (int gate = 0; gate < 4; gate++) {
                const float* p = rb + gate * 8;
                float s = zin[gate];
#pragma unroll
                for (int q = 0; q < NW; q++) s += p[q * 32 * RED_STRIDE];
                z[gate] = s;
            }
            float ig = sigf(z[0]);
            float fg = sigf(z[1]);
            float gg = tanh_fast(z[2]);
            float og = sigf(z[3]);

            c_reg = fg * c_reg + ig * gg;
            float hn = og * tanh_fast(c_reg);
            hcur[eb * H_ + d0 + ed] = __float2bfloat16(hn);
            xres = tanh_fast(hn + xres);     // final output value (stored below)
        }

        // ---- publish h ASAP ----
        __syncthreads();
        if (tid == 0) st_rel(&g_flags[blockIdx.x * 8], (unsigned)(t + 1));

        // ---- off-critical-path: out store + next prefetch ----
        if (tid < 256) {
            out[xi] = xres;
            if (t + 1 < T_) {
#pragma unroll
                for (int gate = 0; gate < 4; gate++)
                    zin[gate] = __ldcg(&g_xz[((size_t)eb * T_ + t + 1) * G4 + gate * H_ + d0 + ed]);
                xi = ((size_t)eb * T_ + t + 1) * H_ + d0 + ed;
                xres = __ldcg(&x[xi]);
            }
        }
    }
}

// ---------------------------------------------------------------------------
extern "C" void kernel_launch(void* const* d_in, const int* in_sizes, int n_in,
                              void* d_out, int out_size) {
    const float* x    = (const float*)d_in[0];
    const float* W    = (const float*)d_in[1];
    const float* U    = (const float*)d_in[2];
    const float* bias = (const float*)d_in[3];
    float* out        = (float*)d_out;

    cudaFuncSetAttribute(lstm_persistent,
                         cudaFuncAttributeMaxDynamicSharedMemorySize, SMEM_BYTES);

    dim3 grid_gemm(G4 / 64, (B_ * T_) / 64);   // (64, 256)
    xw_gemm<<<grid_gemm, 256>>>(x, W, bias);

    lstm_persistent<<<NCTA, NTHREADS, SMEM_BYTES>>>(U, x, out);
}

// round 12
// speedup vs baseline: 1.3080x; 1.0701x over previous
#include <cuda_runtime.h>
#include <cuda_bf16.h>
#include <math.h>

#define B_   32
#define T_   512
#define H_   1024
#define G4   4096   // 4*H

#define NCTA      128
#define NTHREADS  512
#define NW        16

// ---------------------------------------------------------------------------
// Persistent device scratch (no cudaMalloc allowed)
// ---------------------------------------------------------------------------
__device__ float g_xz[(size_t)B_ * T_ * G4];        // [B*T, 4H] input projection
__device__ __nv_bfloat16 g_hbf[2][B_ * H_];         // double-buffered hidden (bf16)
__device__ unsigned g_wflags[NCTA * 8 * 8];         // per-(CTA, gate-warp) stamps, 32B stride

// ---------------------------------------------------------------------------
// helpers
// ---------------------------------------------------------------------------
__device__ __forceinline__ void mma_bf16(float c[4],
                                         unsigned a0, unsigned a1, unsigned a2, unsigned a3,
                                         unsigned b0, unsigned b1) {
    asm volatile(
        "mma.sync.aligned.m16n8k16.row.col.f32.bf16.bf16.f32 "
        "{%0,%1,%2,%3}, {%4,%5,%6,%7}, {%8,%9}, {%0,%1,%2,%3};"
        : "+f"(c[0]), "+f"(c[1]), "+f"(c[2]), "+f"(c[3])
        : "r"(a0), "r"(a1), "r"(a2), "r"(a3), "r"(b0), "r"(b1));
}

__device__ __forceinline__ unsigned pack_bf16(float lo, float hi) {
    __nv_bfloat162 v = __floats2bfloat162_rn(lo, hi);
    return *(unsigned*)&v;
}

__device__ __forceinline__ float sigf(float v) {
    return __fdividef(1.0f, 1.0f + __expf(-v));
}
__device__ __forceinline__ float tanh_fast(float v) {
    return __fdividef(2.0f, 1.0f + __expf(-2.0f * v)) - 1.0f;
}

__device__ __forceinline__ void cp16(unsigned dst_smem, const void* src) {
    asm volatile("cp.async.cg.shared.global [%0], [%1], 16;"
                 :: "r"(dst_smem), "l"(src));
}

__device__ __forceinline__ unsigned ld_acq(const unsigned* p) {
    unsigned v;
    asm volatile("ld.acquire.gpu.global.b32 %0, [%1];" : "=r"(v) : "l"(p));
    return v;
}
__device__ __forceinline__ void st_rel(unsigned* p, unsigned v) {
    asm volatile("st.release.gpu.global.b32 [%0], %1;" :: "l"(p), "r"(v));
}

// ---------------------------------------------------------------------------
// Kernel 1: xz = x @ W + b  via bf16 m16n8k16 (CTA(0,0) re-inits state).
// ---------------------------------------------------------------------------
#define AS32_STRIDE 12
#define BS32_STRIDE 68

__global__ __launch_bounds__(256) void xw_gemm(const float* __restrict__ X,
                                               const float* __restrict__ W,
                                               const float* __restrict__ bias) {
    __shared__ unsigned As32[64 * AS32_STRIDE];
    __shared__ unsigned Bs32[8 * BS32_STRIDE];

    const int tid   = threadIdx.x;
    const int lane  = tid & 31;
    const int w     = tid >> 5;
    const int g     = lane >> 2;
    const int tig   = lane & 3;
    const int warpM = w >> 2;
    const int warpN = w & 3;

    // ---- per-replay state re-init ----
    if (blockIdx.x == 0 && blockIdx.y == 0) {
        unsigned* hz = (unsigned*)g_hbf[0];
        for (int i = tid; i < (B_ * H_) / 2; i += 256) hz[i] = 0u;
        for (int i = tid; i < NCTA * 8 * 8; i += 256) g_wflags[i] = 0u;
    }

    const int row0 = blockIdx.y * 64;
    const int col0 = blockIdx.x * 64;

    const int aRow = tid >> 2;
    const int aC   = tid & 3;
    const int bKp  = tid >> 4;
    const int bNq  = tid & 15;

    float acc[2][2][4];
#pragma unroll
    for (int i = 0; i < 2; i++)
#pragma unroll
        for (int j = 0; j < 2; j++)
#pragma unroll
            for (int k = 0; k < 4; k++) acc[i][j][k] = 0.0f;

    for (int k0 = 0; k0 < H_; k0 += 16) {
        {
            float4 av = *(const float4*)(X + (size_t)(row0 + aRow) * H_ + k0 + 4 * aC);
            uint2 p;
            p.x = pack_bf16(av.x, av.y);
            p.y = pack_bf16(av.z, av.w);
            *(uint2*)(As32 + aRow * AS32_STRIDE + 2 * aC) = p;
        }
        if (tid < 128) {
            const float* wr0 = W + (size_t)(k0 + 2 * bKp)     * G4 + col0 + 4 * bNq;
            const float* wr1 = W + (size_t)(k0 + 2 * bKp + 1) * G4 + col0 + 4 * bNq;
            float4 w0 = *(const float4*)wr0;
            float4 w1 = *(const float4*)wr1;
            uint4 p;
            p.x = pack_bf16(w0.x, w1.x);
            p.y = pack_bf16(w0.y, w1.y);
            p.z = pack_bf16(w0.z, w1.z);
            p.w = pack_bf16(w0.w, w1.w);
            *(uint4*)(Bs32 + bKp * BS32_STRIDE + 4 * bNq) = p;
        }
        __syncthreads();

        unsigned a[2][4];
#pragma unroll
        for (int mi = 0; mi < 2; mi++) {
            const int r = warpM * 32 + mi * 16 + g;
            a[mi][0] = As32[r * AS32_STRIDE + tig];
            a[mi][1] = As32[(r + 8) * AS32_STRIDE + tig];
            a[mi][2] = As32[r * AS32_STRIDE + tig + 4];
            a[mi][3] = As32[(r + 8) * AS32_STRIDE + tig + 4];
        }
#pragma unroll
        for (int ni = 0; ni < 2; ni++) {
            const int n = warpN * 16 + ni * 8 + g;
            unsigned b0 = Bs32[tig * BS32_STRIDE + n];
            unsigned b1 = Bs32[(tig + 4) * BS32_STRIDE + n];
#pragma unroll
            for (int mi = 0; mi < 2; mi++)
                mma_bf16(acc[mi][ni], a[mi][0], a[mi][1], a[mi][2], a[mi][3], b0, b1);
        }
        __syncthreads();
    }

#pragma unroll
    for (int mi = 0; mi < 2; mi++) {
#pragma unroll
        for (int ni = 0; ni < 2; ni++) {
            int row = row0 + warpM * 32 + mi * 16 + g;
            int col = col0 + warpN * 16 + ni * 8 + 2 * tig;
            float2 bvv = *(const float2*)(bias + col);
            float2 v0 = make_float2(acc[mi][ni][0] + bvv.x, acc[mi][ni][1] + bvv.y);
            float2 v1 = make_float2(acc[mi][ni][2] + bvv.x, acc[mi][ni][3] + bvv.y);
            *(float2*)(g_xz + (size_t)row * G4 + col)       = v0;
            *(float2*)(g_xz + (size_t)(row + 8) * G4 + col) = v1;
        }
    }
}

// ---------------------------------------------------------------------------
// Kernel 2: persistent LSTM recurrence, batch-split halves + per-warp flags.
// (Identical to the R11 submission; that round died to broker infra, not to
// the kernel — protocol re-audited for deadlock/WAR before resubmit.)
// CTA cb: half = cb>>6 (batches half*16..+16), dgrp = cb&63 (dims d0=dgrp*16,
// 64 z-cols).  512 threads; warp w: ks = w&7 (k rows [128ks..+128)),
// nh = w>>3 (n cols [nh*32..+32)).
// Producers of warp's k-slice: same-half CTAs 8ks..8ks+8, 8 warp-flags each
// -> 64 flags, 2 per lane.  Warp pair (ks,0)/(ks,1) splits staging, joins
// via named barrier ks+1.  Gate warps (0..7) publish their own flag right
// after their h stores (pre-sync).
// ---------------------------------------------------------------------------
#define HS_STRIDE  1032                    // bf16 per row (1024 + 8 pad)
#define RED_STRIDE 80                      // floats; conflict-free gate reads
#define HS_BYTES   (16 * HS_STRIDE * 2)
#define RED_BYTES  (128 * RED_STRIDE * 4)
#define SMEM_BYTES (HS_BYTES + RED_BYTES)

__global__ __launch_bounds__(NTHREADS, 1) void lstm_persistent(
        const float* __restrict__ U,
        const float* __restrict__ x,
        float* __restrict__ out) {
    extern __shared__ char smem[];
    __nv_bfloat16* hS = (__nv_bfloat16*)smem;          // [16][HS_STRIDE]
    float*        redS = (float*)(smem + HS_BYTES);    // [128][RED_STRIDE]

    const int tid  = threadIdx.x;
    const int lane = tid & 31;
    const int w    = tid >> 5;
    const int ks   = w & 7;       // k-slice (128 rows)
    const int nh   = w >> 3;      // n-half (32 cols)
    const int g    = lane >> 2;
    const int tig  = lane & 3;

    const int half = blockIdx.x >> 6;          // batch half
    const int dgrp = blockIdx.x & 63;
    const int d0   = dgrp * 16;
    const int bb   = half * 16;                // first batch of this half

    // producer flags this lane polls (2 of 64)
    const int i0 = lane * 2, i1 = lane * 2 + 1;
    const unsigned* f0 = &g_wflags[(((half * 64 + 8 * ks + (i0 >> 3)) * 8) + (i0 & 7)) * 8];
    const unsigned* f1 = &g_wflags[(((half * 64 + 8 * ks + (i1 >> 3)) * 8) + (i1 & 7)) * 8];

    // ---- preload U fragments: warp covers n cols nh*32 + ng*8 + g, ng=0..3 ----
    unsigned breg[8][4][2];
#pragma unroll
    for (int kk = 0; kk < 8; kk++) {
#pragma unroll
        for (int ng = 0; ng < 4; ng++) {
            const int j    = nh * 32 + ng * 8 + g;          // z col 0..63
            const int ucol = (j >> 4) * H_ + d0 + (j & 15); // gate*H + dim
            const int k0   = ks * 128 + kk * 16 + 2 * tig;
            breg[kk][ng][0] = pack_bf16(U[(size_t)(k0    ) * G4 + ucol],
                                        U[(size_t)(k0 + 1) * G4 + ucol]);
            breg[kk][ng][1] = pack_bf16(U[(size_t)(k0 + 8) * G4 + ucol],
                                        U[(size_t)(k0 + 9) * G4 + ucol]);
        }
    }

    const int ebl = tid >> 4;    // local batch (gate phase, tid<256)
    const int ed  = tid & 15;    // local dim
    float c_reg = 0.0f;

    float zin[4];
    size_t xi = 0;
    float xres = 0.0f;
    if (tid < 256) {
#pragma unroll
        for (int gate = 0; gate < 4; gate++)
            zin[gate] = __ldcg(&g_xz[((size_t)(bb + ebl) * T_ + 0) * G4 + gate * H_ + d0 + ed]);
        xi = ((size_t)(bb + ebl) * T_ + 0) * H_ + d0 + ed;
        xres = __ldcg(&x[xi]);
    }

    for (int t = 0; t < T_; t++) {
        const unsigned need = (unsigned)t;
        const __nv_bfloat16* hprev = g_hbf[t & 1];
        __nv_bfloat16*       hcur  = g_hbf[(t + 1) & 1];

        // ---- dataflow wait: this warp's 64 producer-warp flags ----
        for (;;) {
            bool ok = (ld_acq(f0) >= need) && (ld_acq(f1) >= need);
            if (__all_sync(0xffffffffu, ok)) break;
        }

        // ---- stage warp's half of the k-slice: rows nh*8..nh*8+8, 2KB ----
#pragma unroll
        for (int i = 0; i < 4; i++) {
            int q = i * 32 + lane;            // 0..127
            int r = nh * 8 + (q >> 4);        // local batch row
            int c = q & 15;                   // 16B chunk in 256B row-slice
            cp16((unsigned)__cvta_generic_to_shared(hS + r * HS_STRIDE + ks * 128 + c * 8),
                 hprev + (size_t)(bb + r) * H_ + ks * 128 + c * 8);
        }
        asm volatile("cp.async.commit_group;");
        asm volatile("cp.async.wait_group 0;" ::: "memory");
        // join warp pair (both need all 16 rows)
        asm volatile("bar.sync %0, %1;" :: "r"(ks + 1), "r"(64) : "memory");

        // ---- z partials: [16 x 32] over 128-k slice ----
        float acc[4][4];
#pragma unroll
        for (int ng = 0; ng < 4; ng++)
#pragma unroll
            for (int q = 0; q < 4; q++) acc[ng][q] = 0.0f;

#pragma unroll
        for (int kk = 0; kk < 8; kk++) {
            const int kcol = ks * 128 + kk * 16 + 2 * tig;
            const __nv_bfloat16* r0 = hS + g * HS_STRIDE;
            const __nv_bfloat16* r1 = hS + (g + 8) * HS_STRIDE;
            unsigned a0 = *(const unsigned*)(r0 + kcol);
            unsigned a1 = *(const unsigned*)(r1 + kcol);
            unsigned a2 = *(const unsigned*)(r0 + kcol + 8);
            unsigned a3 = *(const unsigned*)(r1 + kcol + 8);
#pragma unroll
            for (int ng = 0; ng < 4; ng++)
                mma_bf16(acc[ng], a0, a1, a2, a3, breg[kk][ng][0], breg[kk][ng][1]);
        }

        // ---- write k-partials: rows ks*16 + {g, g+8}, cols nh*32 + ng*8 + 2tig ----
#pragma unroll
        for (int ng = 0; ng < 4; ng++) {
            const int col = nh * 32 + ng * 8 + 2 * tig;
            float* r0 = redS + (ks * 16 + g)     * RED_STRIDE + col;
            float* r1 = redS + (ks * 16 + g + 8) * RED_STRIDE + col;
            *(float2*)r0 = make_float2(acc[ng][0], acc[ng][1]);
            *(float2*)r1 = make_float2(acc[ng][2], acc[ng][3]);
        }
        __syncthreads();

        // ---- gates + state + early per-warp publish (tid < 256) ----
        if (tid < 256) {
            const float* rb = redS + ebl * RED_STRIDE + ed;
            float z[4];
#pragma unroll
            for (int gate = 0; gate < 4; gate++) {
                const float* p = rb + gate * 16;
                float s = zin[gate];
#pragma unroll
                for (int q = 0; q < 8; q++) s += p[q * 16 * RED_STRIDE];
                z[gate] = s;
            }
            float ig = sigf(z[0]);
            float fg = sigf(z[1]);
            float gg = tanh_fast(z[2]);
            float og = sigf(z[3]);

            c_reg = fg * c_reg + ig * gg;
            float hn = og * tanh_fast(c_reg);
            __stcg(&hcur[(size_t)(bb + ebl) * H_ + d0 + ed], __float2bfloat16(hn));

            // publish this gate warp's stamp (h stores above ordered by syncwarp)
            __syncwarp();
            if (lane == 0)
                st_rel(&g_wflags[((blockIdx.x * 8) + w) * 8], (unsigned)(t + 1));

            // off-critical-path
            out[xi] = tanh_fast(hn + xres);
            if (t + 1 < T_) {
#pragma unroll
                for (int gate = 0; gate < 4; gate++)
                    zin[gate] = __ldcg(&g_xz[((size_t)(bb + ebl) * T_ + t + 1) * G4 + gate * H_ + d0 + ed]);
                xi = ((size_t)(bb + ebl) * T_ + t + 1) * H_ + d0 + ed;
                xres = __ldcg(&x[xi]);
            }
        }
        __syncthreads();   // redS + hS WAR protection
    }
}

// ---------------------------------------------------------------------------
extern "C" void kernel_launch(void* const* d_in, const int* in_sizes, int n_in,
                              void* d_out, int out_size) {
    const float* x    = (const float*)d_in[0];
    const float* W    = (const float*)d_in[1];
    const float* U    = (const float*)d_in[2];
    const float* bias = (const float*)d_in[3];
    float* out        = (float*)d_out;

    cudaFuncSetAttribute(lstm_persistent,
                         cudaFuncAttributeMaxDynamicSharedMemorySize, SMEM_BYTES);

    dim3 grid_gemm(G4 / 64, (B_ * T_) / 64);   // (64, 256)
    xw_gemm<<<grid_gemm, 256>>>(x, W, bias);

    lstm_persistent<<<NCTA, NTHREADS, SMEM_BYTES>>>(U, x, out);
}

// round 13
// speedup vs baseline: 1.4604x; 1.1165x over previous
#include <cuda_runtime.h>
#include <cuda_bf16.h>
#include <math.h>

#define B_   32
#define T_   512
#define H_   1024
#define G4   4096   // 4*H

#define NCTA      128
#define NTHREADS  512

// ---------------------------------------------------------------------------
// Persistent device scratch (no cudaMalloc allowed)
// ---------------------------------------------------------------------------
__device__ float g_xz[(size_t)B_ * T_ * G4];        // [B*T, 4H] input projection
__device__ __nv_bfloat16 g_hbf[2][B_ * H_];         // double-buffered hidden (bf16)
__device__ unsigned g_flags[NCTA * 8];              // one stamp per CTA, 32B stride

// ---------------------------------------------------------------------------
// helpers
// ---------------------------------------------------------------------------
__device__ __forceinline__ void mma_bf16(float c[4],
                                         unsigned a0, unsigned a1, unsigned a2, unsigned a3,
                                         unsigned b0, unsigned b1) {
    asm volatile(
        "mma.sync.aligned.m16n8k16.row.col.f32.bf16.bf16.f32 "
        "{%0,%1,%2,%3}, {%4,%5,%6,%7}, {%8,%9}, {%0,%1,%2,%3};"
        : "+f"(c[0]), "+f"(c[1]), "+f"(c[2]), "+f"(c[3])
        : "r"(a0), "r"(a1), "r"(a2), "r"(a3), "r"(b0), "r"(b1));
}

__device__ __forceinline__ unsigned pack_bf16(float lo, float hi) {
    __nv_bfloat162 v = __floats2bfloat162_rn(lo, hi);
    return *(unsigned*)&v;
}

__device__ __forceinline__ float sigf(float v) {
    return __fdividef(1.0f, 1.0f + __expf(-v));
}
__device__ __forceinline__ float tanh_fast(float v) {
    return __fdividef(2.0f, 1.0f + __expf(-2.0f * v)) - 1.0f;
}

__device__ __forceinline__ void cp16(unsigned dst_smem, const void* src) {
    asm volatile("cp.async.cg.shared.global [%0], [%1], 16;"
                 :: "r"(dst_smem), "l"(src));
}

__device__ __forceinline__ unsigned ld_acq(const unsigned* p) {
    unsigned v;
    asm volatile("ld.acquire.gpu.global.b32 %0, [%1];" : "=r"(v) : "l"(p));
    return v;
}
__device__ __forceinline__ void st_rel(unsigned* p, unsigned v) {
    asm volatile("st.release.gpu.global.b32 [%0], %1;" :: "l"(p), "r"(v));
}

// ---------------------------------------------------------------------------
// Kernel 1: xz = x @ W + b  via bf16 m16n8k16 (CTA(0,0) re-inits state).
// ---------------------------------------------------------------------------
#define AS32_STRIDE 12
#define BS32_STRIDE 68

__global__ __launch_bounds__(256) void xw_gemm(const float* __restrict__ X,
                                               const float* __restrict__ W,
                                               const float* __restrict__ bias) {
    __shared__ unsigned As32[64 * AS32_STRIDE];
    __shared__ unsigned Bs32[8 * BS32_STRIDE];

    const int tid   = threadIdx.x;
    const int lane  = tid & 31;
    const int w     = tid >> 5;
    const int g     = lane >> 2;
    const int tig   = lane & 3;
    const int warpM = w >> 2;
    const int warpN = w & 3;

    // ---- per-replay state re-init ----
    if (blockIdx.x == 0 && blockIdx.y == 0) {
        unsigned* hz = (unsigned*)g_hbf[0];
        for (int i = tid; i < (B_ * H_) / 2; i += 256) hz[i] = 0u;
        for (int i = tid; i < NCTA * 8; i += 256) g_flags[i] = 0u;
    }

    const int row0 = blockIdx.y * 64;
    const int col0 = blockIdx.x * 64;

    const int aRow = tid >> 2;
    const int aC   = tid & 3;
    const int bKp  = tid >> 4;
    const int bNq  = tid & 15;

    float acc[2][2][4];
#pragma unroll
    for (int i = 0; i < 2; i++)
#pragma unroll
        for (int j = 0; j < 2; j++)
#pragma unroll
            for (int k = 0; k < 4; k++) acc[i][j][k] = 0.0f;

    for (int k0 = 0; k0 < H_; k0 += 16) {
        {
            float4 av = *(const float4*)(X + (size_t)(row0 + aRow) * H_ + k0 + 4 * aC);
            uint2 p;
            p.x = pack_bf16(av.x, av.y);
            p.y = pack_bf16(av.z, av.w);
            *(uint2*)(As32 + aRow * AS32_STRIDE + 2 * aC) = p;
        }
        if (tid < 128) {
            const float* wr0 = W + (size_t)(k0 + 2 * bKp)     * G4 + col0 + 4 * bNq;
            const float* wr1 = W + (size_t)(k0 + 2 * bKp + 1) * G4 + col0 + 4 * bNq;
            float4 w0 = *(const float4*)wr0;
            float4 w1 = *(const float4*)wr1;
            uint4 p;
            p.x = pack_bf16(w0.x, w1.x);
            p.y = pack_bf16(w0.y, w1.y);
            p.z = pack_bf16(w0.z, w1.z);
            p.w = pack_bf16(w0.w, w1.w);
            *(uint4*)(Bs32 + bKp * BS32_STRIDE + 4 * bNq) = p;
        }
        __syncthreads();

        unsigned a[2][4];
#pragma unroll
        for (int mi = 0; mi < 2; mi++) {
            const int r = warpM * 32 + mi * 16 + g;
            a[mi][0] = As32[r * AS32_STRIDE + tig];
            a[mi][1] = As32[(r + 8) * AS32_STRIDE + tig];
            a[mi][2] = As32[r * AS32_STRIDE + tig + 4];
            a[mi][3] = As32[(r + 8) * AS32_STRIDE + tig + 4];
        }
#pragma unroll
        for (int ni = 0; ni < 2; ni++) {
            const int n = warpN * 16 + ni * 8 + g;
            unsigned b0 = Bs32[tig * BS32_STRIDE + n];
            unsigned b1 = Bs32[(tig + 4) * BS32_STRIDE + n];
#pragma unroll
            for (int mi = 0; mi < 2; mi++)
                mma_bf16(acc[mi][ni], a[mi][0], a[mi][1], a[mi][2], a[mi][3], b0, b1);
        }
        __syncthreads();
    }

#pragma unroll
    for (int mi = 0; mi < 2; mi++) {
#pragma unroll
        for (int ni = 0; ni < 2; ni++) {
            int row = row0 + warpM * 32 + mi * 16 + g;
            int col = col0 + warpN * 16 + ni * 8 + 2 * tig;
            float2 bvv = *(const float2*)(bias + col);
            float2 v0 = make_float2(acc[mi][ni][0] + bvv.x, acc[mi][ni][1] + bvv.y);
            float2 v1 = make_float2(acc[mi][ni][2] + bvv.x, acc[mi][ni][3] + bvv.y);
            *(float2*)(g_xz + (size_t)row * G4 + col)       = v0;
            *(float2*)(g_xz + (size_t)(row + 8) * G4 + col) = v1;
        }
    }
}

// ---------------------------------------------------------------------------
// Kernel 2: persistent LSTM recurrence, batch-split halves, single CTA flag,
// low-traffic polling (only nh=0 warps poll; they also stage the full slice).
// CTA cb: half = cb>>6 (batches half*16..+16), dgrp = cb&63 (d0=dgrp*16).
// Warp w: ks = w&7 (k rows [128ks..+128)), nh = w>>3 (n cols [nh*32..+32)).
// Step: [nh=0: poll 8 producer CTA flags (lane<8), cp.async 16x128k slice]
//       named-bar pair join -> MMA -> STS partials -> sync#1 ->
//       gates (warps 0-7) -> h stores -> sync#2 -> tid0 publish -> prefetch.
// WAR: all next-step STS are after sync#2; all redS gate-reads before sync#2.
// ---------------------------------------------------------------------------
#define HS_STRIDE  1032                    // bf16 per row (1024 + 8 pad)
#define RED_STRIDE 80                      // floats; conflict-free gate reads
#define HS_BYTES   (16 * HS_STRIDE * 2)
#define RED_BYTES  (128 * RED_STRIDE * 4)
#define SMEM_BYTES (HS_BYTES + RED_BYTES)

__global__ __launch_bounds__(NTHREADS, 1) void lstm_persistent(
        const float* __restrict__ U,
        const float* __restrict__ x,
        float* __restrict__ out) {
    extern __shared__ char smem[];
    __nv_bfloat16* hS = (__nv_bfloat16*)smem;          // [16][HS_STRIDE]
    float*        redS = (float*)(smem + HS_BYTES);    // [128][RED_STRIDE]

    const int tid  = threadIdx.x;
    const int lane = tid & 31;
    const int w    = tid >> 5;
    const int ks   = w & 7;       // k-slice (128 rows)
    const int nh   = w >> 3;      // n-half (32 cols)
    const int g    = lane >> 2;
    const int tig  = lane & 3;

    const int half = blockIdx.x >> 6;
    const int dgrp = blockIdx.x & 63;
    const int d0   = dgrp * 16;
    const int bb   = half * 16;

    // producer flag this lane polls (nh=0 warps, lanes 0..7)
    const unsigned* pflag = &g_flags[(half * 64 + 8 * ks + (lane & 7)) * 8];

    // ---- preload U fragments: warp covers n cols nh*32 + ng*8 + g ----
    unsigned breg[8][4][2];
#pragma unroll
    for (int kk = 0; kk < 8; kk++) {
#pragma unroll
        for (int ng = 0; ng < 4; ng++) {
            const int j    = nh * 32 + ng * 8 + g;
            const int ucol = (j >> 4) * H_ + d0 + (j & 15);
            const int k0   = ks * 128 + kk * 16 + 2 * tig;
            breg[kk][ng][0] = pack_bf16(U[(size_t)(k0    ) * G4 + ucol],
                                        U[(size_t)(k0 + 1) * G4 + ucol]);
            breg[kk][ng][1] = pack_bf16(U[(size_t)(k0 + 8) * G4 + ucol],
                                        U[(size_t)(k0 + 9) * G4 + ucol]);
        }
    }

    const int ebl = tid >> 4;    // local batch (gate phase, tid<256)
    const int ed  = tid & 15;    // local dim
    float c_reg = 0.0f;

    float zin[4];
    size_t xi = 0;
    float xres = 0.0f;
    if (tid < 256) {
#pragma unroll
        for (int gate = 0; gate < 4; gate++)
            zin[gate] = __ldcg(&g_xz[((size_t)(bb + ebl) * T_ + 0) * G4 + gate * H_ + d0 + ed]);
        xi = ((size_t)(bb + ebl) * T_ + 0) * H_ + d0 + ed;
        xres = __ldcg(&x[xi]);
    }

    for (int t = 0; t < T_; t++) {
        const unsigned need = (unsigned)t;
        const __nv_bfloat16* hprev = g_hbf[t & 1];
        __nv_bfloat16*       hcur  = g_hbf[(t + 1) & 1];

        if (nh == 0) {
            // ---- poll this warp's 8 producer CTA flags (lanes 0..7) ----
            for (;;) {
                bool ok = (lane >= 8) || (ld_acq(pflag) >= need);
                if (__all_sync(0xffffffffu, ok)) break;
            }
            // ---- stage full k-slice: 16 rows x 128 k (4KB), 8 cp16/lane ----
#pragma unroll
            for (int i = 0; i < 8; i++) {
                int q = i * 32 + lane;            // 0..255
                int r = q >> 4;                   // local batch row 0..15
                int c = q & 15;                   // 16B chunk in 256B row-slice
                cp16((unsigned)__cvta_generic_to_shared(hS + r * HS_STRIDE + ks * 128 + c * 8),
                     hprev + (size_t)(bb + r) * H_ + ks * 128 + c * 8);
            }
            asm volatile("cp.async.commit_group;");
            asm volatile("cp.async.wait_group 0;" ::: "memory");
        }
        // pair join: nh=1 waits here during poll+stage
        asm volatile("bar.sync %0, %1;" :: "r"(ks + 1), "r"(64) : "memory");

        // ---- z partials: [16 x 32] over 128-k slice ----
        float acc[4][4];
#pragma unroll
        for (int ng = 0; ng < 4; ng++)
#pragma unroll
            for (int q = 0; q < 4; q++) acc[ng][q] = 0.0f;

#pragma unroll
        for (int kk = 0; kk < 8; kk++) {
            const int kcol = ks * 128 + kk * 16 + 2 * tig;
            const __nv_bfloat16* r0 = hS + g * HS_STRIDE;
            const __nv_bfloat16* r1 = hS + (g + 8) * HS_STRIDE;
            unsigned a0 = *(const unsigned*)(r0 + kcol);
            unsigned a1 = *(const unsigned*)(r1 + kcol);
            unsigned a2 = *(const unsigned*)(r0 + kcol + 8);
            unsigned a3 = *(const unsigned*)(r1 + kcol + 8);
#pragma unroll
            for (int ng = 0; ng < 4; ng++)
                mma_bf16(acc[ng], a0, a1, a2, a3, breg[kk][ng][0], breg[kk][ng][1]);
        }

        // ---- write k-partials ----
#pragma unroll
        for (int ng = 0; ng < 4; ng++) {
            const int col = nh * 32 + ng * 8 + 2 * tig;
            float* r0 = redS + (ks * 16 + g)     * RED_STRIDE + col;
            float* r1 = redS + (ks * 16 + g + 8) * RED_STRIDE + col;
            *(float2*)r0 = make_float2(acc[ng][0], acc[ng][1]);
            *(float2*)r1 = make_float2(acc[ng][2], acc[ng][3]);
        }
        __syncthreads();                                   // sync#1

        // ---- gates + state (warps 0-7) ----
        if (tid < 256) {
            const float* rb = redS + ebl * RED_STRIDE + ed;
            float z[4];
#pragma unroll
            for (int gate = 0; gate < 4; gate++) {
                const float* p = rb + gate * 16;
                float s = zin[gate];
#pragma unroll
                for (int q = 0; q < 8; q++) s += p[q * 16 * RED_STRIDE];
                z[gate] = s;
            }
            float ig = sigf(z[0]);
            float fg = sigf(z[1]);
            float gg = tanh_fast(z[2]);
            float og = sigf(z[3]);

            c_reg = fg * c_reg + ig * gg;
            float hn = og * tanh_fast(c_reg);
            __stcg(&hcur[(size_t)(bb + ebl) * H_ + d0 + ed], __float2bfloat16(hn));
            xres = tanh_fast(hn + xres);     // final output value (stored below)
        }
        __syncthreads();                                   // sync#2

        // ---- publish CTA stamp (cumulative release covers all h stores) ----
        if (tid == 0) st_rel(&g_flags[blockIdx.x * 8], (unsigned)(t + 1));

        // ---- off-critical-path: out store + next prefetch ----
        if (tid < 256) {
            out[xi] = xres;
            if (t + 1 < T_) {
#pragma unroll
                for (int gate = 0; gate < 4; gate++)
                    zin[gate] = __ldcg(&g_xz[((size_t)(bb + ebl) * T_ + t + 1) * G4 + gate * H_ + d0 + ed]);
                xi = ((size_t)(bb + ebl) * T_ + t + 1) * H_ + d0 + ed;
                xres = __ldcg(&x[xi]);
            }
        }
        // no third sync: all next-step STS paths pass sync#2 (directly, or
        // via named bar whose nh=0 partner passed sync#2)
    }
}

// ---------------------------------------------------------------------------
extern "C" void kernel_launch(void* const* d_in, const int* in_sizes, int n_in,
                              void* d_out, int out_size) {
    const float* x    = (const float*)d_in[0];
    const float* W    = (const float*)d_in[1];
    const float* U    = (const float*)d_in[2];
    const float* bias = (const float*)d_in[3];
    float* out        = (float*)d_out;

    cudaFuncSetAttribute(lstm_persistent,
                         cudaFuncAttributeMaxDynamicSharedMemorySize, SMEM_BYTES);

    dim3 grid_gemm(G4 / 64, (B_ * T_) / 64);   // (64, 256)
    xw_gemm<<<grid_gemm, 256>>>(x, W, bias);

    lstm_persistent<<<NCTA, NTHREADS, SMEM_BYTES>>>(U, x, out);
}